// round 1
// baseline (speedup 1.0000x reference)
#include <cuda_runtime.h>
#include <cstdint>

// Problem constants (fixed by the reference)
constexpr int IMG_H = 256;       // NX (rows, indexed by gy)
constexpr int IMG_W = 256;       // NY (cols, indexed by gx)
constexpr int NDET  = 368;
constexpr int NVIEW = 180;
constexpr int NSAMP = 513;       // NX + NY + 1
constexpr int NRAY  = NDET * NVIEW;   // 66240

__global__ __launch_bounds__(256, 8)
void fp_kernel(const float* __restrict__ img,
               const float2* __restrict__ grid,   // [NRAY, NSAMP] of (gx, gy)
               const float* __restrict__ wt,      // [NRAY, NSAMP]
               float* __restrict__ out)           // [NRAY]
{
    const int ray = blockIdx.x;
    const float2* __restrict__ g = grid + (size_t)ray * NSAMP;
    const float*  __restrict__ w = wt   + (size_t)ray * NSAMP;

    float acc = 0.0f;

    #pragma unroll 1
    for (int s = threadIdx.x; s < NSAMP; s += 256) {
        const float2 p   = __ldg(&g[s]);
        const float  wgt = __ldg(&w[s]);

        // grid_sample bilinear, align_corners=False:
        // ix = ((gx + 1) * W - 1) * 0.5
        float ix = fmaf(p.x, 128.0f, 127.5f);   // ((x+1)*256-1)*0.5 = 128x + 127.5
        float iy = fmaf(p.y, 128.0f, 127.5f);

        float fx = floorf(ix);
        float fy = floorf(iy);
        int x0 = (int)fx;
        int y0 = (int)fy;
        float wx1 = ix - fx;
        float wy1 = iy - fy;
        float wx0 = 1.0f - wx1;
        float wy0 = 1.0f - wy1;

        const int x1 = x0 + 1;
        const int y1 = y0 + 1;

        const bool vx0 = (x0 >= 0) & (x0 < IMG_W);
        const bool vx1 = (x1 >= 0) & (x1 < IMG_W);
        const bool vy0 = (y0 >= 0) & (y0 < IMG_H);
        const bool vy1 = (y1 >= 0) & (y1 < IMG_H);

        float v00 = (vx0 & vy0) ? __ldg(&img[y0 * IMG_W + x0]) : 0.0f;
        float v10 = (vx1 & vy0) ? __ldg(&img[y0 * IMG_W + x1]) : 0.0f;
        float v01 = (vx0 & vy1) ? __ldg(&img[y1 * IMG_W + x0]) : 0.0f;
        float v11 = (vx1 & vy1) ? __ldg(&img[y1 * IMG_W + x1]) : 0.0f;

        float top = fmaf(wx1, v10, wx0 * v00);
        float bot = fmaf(wx1, v11, wx0 * v01);
        acc = fmaf(wgt, fmaf(wy1, bot, wy0 * top), acc);
    }

    // Block reduction: 8 warps of 32
    #pragma unroll
    for (int o = 16; o > 0; o >>= 1)
        acc += __shfl_down_sync(0xFFFFFFFFu, acc, o);

    __shared__ float sred[8];
    const int lane = threadIdx.x & 31;
    const int wid  = threadIdx.x >> 5;
    if (lane == 0) sred[wid] = acc;
    __syncthreads();

    if (threadIdx.x < 8) {
        float v = sred[threadIdx.x];
        #pragma unroll
        for (int o = 4; o > 0; o >>= 1)
            v += __shfl_down_sync(0x000000FFu, v, o);
        if (threadIdx.x == 0) out[ray] = v;
    }
}

extern "C" void kernel_launch(void* const* d_in, const int* in_sizes, int n_in,
                              void* d_out, int out_size)
{
    const float*  img  = (const float*)d_in[0];   // [1,1,256,256]
    const float2* grid = (const float2*)d_in[1];  // [368,180,513,2]
    const float*  wt   = (const float*)d_in[2];   // [1,1,368,180,513]
    float* out = (float*)d_out;                   // [1,1,368,180]

    (void)in_sizes; (void)n_in; (void)out_size;

    fp_kernel<<<NRAY, 256>>>(img, grid, wt, out);
}

// round 5
// speedup vs baseline: 1.0922x; 1.0922x over previous
#include <cuda_runtime.h>
#include <cstdint>

constexpr int IMG_N  = 256;           // square image
constexpr int NDET   = 368;
constexpr int NVIEW  = 180;
constexpr int NSAMP  = 513;
constexpr int NRAY   = NDET * NVIEW;  // 66240

// Transposed copy of the image (scratch; allocation-free per harness rules)
__device__ float g_imgT[IMG_N * IMG_N];

__global__ void transpose_kernel(const float* __restrict__ img)
{
    __shared__ float tile[32][33];
    const int x = blockIdx.x * 32 + threadIdx.x;
    const int y = blockIdx.y * 32 + threadIdx.y;
    tile[threadIdx.y][threadIdx.x] = img[y * IMG_N + x];
    __syncthreads();
    const int tx = blockIdx.y * 32 + threadIdx.x;
    const int ty = blockIdx.x * 32 + threadIdx.y;
    g_imgT[ty * IMG_N + tx] = tile[threadIdx.x][threadIdx.y];
}

// Bilinear sample with zeros padding. 'u' is the memory-contiguous (fast)
// coordinate, 'v' the slow one; index = v*256 + u.
__device__ __forceinline__ float bilin(const float* __restrict__ im,
                                       float u, float v, float wgt)
{
    // grid_sample align_corners=False: i = ((g+1)*256 - 1)*0.5 = 128*g + 127.5
    const float iu = fmaf(u, 128.0f, 127.5f);
    const float iv = fmaf(v, 128.0f, 127.5f);
    const float fu = floorf(iu);
    const float fv = floorf(iv);
    const int u0 = (int)fu, v0 = (int)fv;
    const int u1 = u0 + 1,  v1 = v0 + 1;
    const float wu1 = iu - fu, wv1 = iv - fv;
    const float wu0 = 1.0f - wu1, wv0 = 1.0f - wv1;

    const bool bu0 = (u0 >= 0) & (u0 < IMG_N);
    const bool bu1 = (u1 >= 0) & (u1 < IMG_N);
    const bool bv0 = (v0 >= 0) & (v0 < IMG_N);
    const bool bv1 = (v1 >= 0) & (v1 < IMG_N);

    const float a00 = (bu0 & bv0) ? __ldg(&im[v0 * IMG_N + u0]) : 0.0f;
    const float a10 = (bu1 & bv0) ? __ldg(&im[v0 * IMG_N + u1]) : 0.0f;
    const float a01 = (bu0 & bv1) ? __ldg(&im[v1 * IMG_N + u0]) : 0.0f;
    const float a11 = (bu1 & bv1) ? __ldg(&im[v1 * IMG_N + u1]) : 0.0f;

    const float top = fmaf(wu1, a10, wu0 * a00);
    const float bot = fmaf(wu1, a11, wu0 * a01);
    return wgt * fmaf(wv1, bot, wv0 * top);
}

__global__ __launch_bounds__(256, 8)
void fp_kernel(const float* __restrict__ img,
               const float2* __restrict__ grid,   // [NRAY, NSAMP] (gx, gy)
               const float* __restrict__ wt,      // [NRAY, NSAMP]
               float* __restrict__ out)           // [NRAY]
{
    const int ray = blockIdx.x;
    const float2* __restrict__ g = grid + (size_t)ray * NSAMP;
    const float*  __restrict__ w = wt   + (size_t)ray * NSAMP;

    // Per-ray orientation: pick the image copy whose contiguous axis matches
    // the fast-moving coordinate along the ray.
    __shared__ int s_mode;
    if (threadIdx.x == 0) {
        const float2 a = __ldg(&g[0]);
        const float2 b = __ldg(&g[NSAMP - 1]);
        s_mode = (fabsf(b.x - a.x) >= fabsf(b.y - a.y)) ? 0 : 1;
    }
    __syncthreads();
    const bool tr = (s_mode != 0);
    const float* __restrict__ im = tr ? g_imgT : img;

    // 513 samples = 256*2 + 1. Each thread: s=tid, s=tid+256; thread 0 also s=512.
    const int s1 = threadIdx.x;
    const int s2 = threadIdx.x + 256;

    // Front-load all streaming reads (streaming hint: keep L1 for the image).
    const float2 p1 = __ldcs(&g[s1]);
    const float  w1 = __ldcs(&w[s1]);
    const float2 p2 = __ldcs(&g[s2]);
    const float  w2 = __ldcs(&w[s2]);

    float2 p3 = make_float2(0.0f, 0.0f);
    float  w3 = 0.0f;
    if (threadIdx.x == 0) {
        p3 = __ldcs(&g[512]);
        w3 = __ldcs(&w[512]);
    }

    float acc;
    if (tr) {
        acc  = bilin(im, p1.y, p1.x, w1);
        acc += bilin(im, p2.y, p2.x, w2);
        if (threadIdx.x == 0) acc += bilin(im, p3.y, p3.x, w3);
    } else {
        acc  = bilin(im, p1.x, p1.y, w1);
        acc += bilin(im, p2.x, p2.y, w2);
        if (threadIdx.x == 0) acc += bilin(im, p3.x, p3.y, w3);
    }

    // Block reduction: 8 warps of 32
    #pragma unroll
    for (int o = 16; o > 0; o >>= 1)
        acc += __shfl_down_sync(0xFFFFFFFFu, acc, o);

    __shared__ float sred[8];
    const int lane = threadIdx.x & 31;
    const int wid  = threadIdx.x >> 5;
    if (lane == 0) sred[wid] = acc;
    __syncthreads();

    if (threadIdx.x < 8) {
        float v = sred[threadIdx.x];
        #pragma unroll
        for (int o = 4; o > 0; o >>= 1)
            v += __shfl_down_sync(0x000000FFu, v, o);
        if (threadIdx.x == 0) out[ray] = v;
    }
}

extern "C" void kernel_launch(void* const* d_in, const int* in_sizes, int n_in,
                              void* d_out, int out_size)
{
    const float*  img  = (const float*)d_in[0];   // [1,1,256,256]
    const float2* grid = (const float2*)d_in[1];  // [368,180,513,2]
    const float*  wt   = (const float*)d_in[2];   // [1,1,368,180,513]
    float* out = (float*)d_out;                   // [1,1,368,180]
    (void)in_sizes; (void)n_in; (void)out_size;

    transpose_kernel<<<dim3(IMG_N / 32, IMG_N / 32), dim3(32, 32)>>>(img);
    fp_kernel<<<NRAY, 256>>>(img, grid, wt, out);
}

// round 6
// speedup vs baseline: 1.1468x; 1.0500x over previous
#include <cuda_runtime.h>
#include <cstdint>

constexpr int IMG_N  = 256;           // square image
constexpr int NDET   = 368;
constexpr int NVIEW  = 180;
constexpr int NSAMP  = 513;
constexpr int NRAY   = NDET * NVIEW;  // 66240
constexpr int RAYS_PER_BLOCK = 8;     // one warp per ray

// Transposed copy of the image (scratch; allocation-free per harness rules)
__device__ float g_imgT[IMG_N * IMG_N];

__global__ void transpose_kernel(const float* __restrict__ img)
{
    __shared__ float tile[32][33];
    const int x = blockIdx.x * 32 + threadIdx.x;
    const int y = blockIdx.y * 32 + threadIdx.y;
    tile[threadIdx.y][threadIdx.x] = img[y * IMG_N + x];
    __syncthreads();
    const int tx = blockIdx.y * 32 + threadIdx.x;
    const int ty = blockIdx.x * 32 + threadIdx.y;
    g_imgT[ty * IMG_N + tx] = tile[threadIdx.x][threadIdx.y];
}

// Bilinear sample with zeros padding. 'u' is the memory-contiguous (fast)
// coordinate; index = v*256 + u.
__device__ __forceinline__ float bilin(const float* __restrict__ im,
                                       float u, float v, float wgt)
{
    // grid_sample align_corners=False: i = ((g+1)*256 - 1)*0.5 = 128*g + 127.5
    const float iu = fmaf(u, 128.0f, 127.5f);
    const float iv = fmaf(v, 128.0f, 127.5f);
    const float fu = floorf(iu);
    const float fv = floorf(iv);
    const int u0 = (int)fu, v0 = (int)fv;
    const int u1 = u0 + 1,  v1 = v0 + 1;
    const float wu1 = iu - fu, wv1 = iv - fv;
    const float wu0 = 1.0f - wu1, wv0 = 1.0f - wv1;

    const bool bu0 = (u0 >= 0) & (u0 < IMG_N);
    const bool bu1 = (u1 >= 0) & (u1 < IMG_N);
    const bool bv0 = (v0 >= 0) & (v0 < IMG_N);
    const bool bv1 = (v1 >= 0) & (v1 < IMG_N);

    const float a00 = (bu0 & bv0) ? __ldg(&im[v0 * IMG_N + u0]) : 0.0f;
    const float a10 = (bu1 & bv0) ? __ldg(&im[v0 * IMG_N + u1]) : 0.0f;
    const float a01 = (bu0 & bv1) ? __ldg(&im[v1 * IMG_N + u0]) : 0.0f;
    const float a11 = (bu1 & bv1) ? __ldg(&im[v1 * IMG_N + u1]) : 0.0f;

    const float top = fmaf(wu1, a10, wu0 * a00);
    const float bot = fmaf(wu1, a11, wu0 * a01);
    return wgt * fmaf(wv1, bot, wv0 * top);
}

__global__ __launch_bounds__(256)
void fp_kernel(const float* __restrict__ img,
               const float2* __restrict__ grid,   // [NRAY, NSAMP] (gx, gy)
               const float* __restrict__ wt,      // [NRAY, NSAMP]
               float* __restrict__ out)           // [NRAY]
{
    const int wid  = threadIdx.x >> 5;
    const int lane = threadIdx.x & 31;
    const int ray  = blockIdx.x * RAYS_PER_BLOCK + wid;

    const float2* __restrict__ g = grid + (size_t)ray * NSAMP;
    const float*  __restrict__ w = wt   + (size_t)ray * NSAMP;

    // Per-ray orientation (uniform across the warp; broadcast loads are free).
    const float2 ga = __ldg(&g[0]);
    const float2 gb = __ldg(&g[NSAMP - 1]);
    const bool   tr = fabsf(gb.x - ga.x) < fabsf(gb.y - ga.y);
    const float* __restrict__ im = tr ? g_imgT : img;

    float acc = 0.0f;

    // 512 samples per warp in 4 chunks of 4 strided batches: s = lane + 32*k.
    #pragma unroll
    for (int c = 0; c < 4; c++) {
        float2 p[4];
        float  pw[4];
        #pragma unroll
        for (int j = 0; j < 4; j++) {
            const int s = lane + 32 * (c * 4 + j);
            p[j]  = __ldcs(&g[s]);
            pw[j] = __ldcs(&w[s]);
        }
        #pragma unroll
        for (int j = 0; j < 4; j++) {
            const float u = tr ? p[j].y : p[j].x;
            const float v = tr ? p[j].x : p[j].y;
            acc += bilin(im, u, v, pw[j]);
        }
    }

    // Sample 512 (the odd one): lane 0 only.
    if (lane == 0) {
        const float2 p = __ldg(&g[512]);
        const float  wv = __ldg(&w[512]);
        acc += bilin(im, tr ? p.y : p.x, tr ? p.x : p.y, wv);
    }

    // Warp reduction — no smem, no syncthreads.
    #pragma unroll
    for (int o = 16; o > 0; o >>= 1)
        acc += __shfl_down_sync(0xFFFFFFFFu, acc, o);

    if (lane == 0) out[ray] = acc;
}

extern "C" void kernel_launch(void* const* d_in, const int* in_sizes, int n_in,
                              void* d_out, int out_size)
{
    const float*  img  = (const float*)d_in[0];   // [1,1,256,256]
    const float2* grid = (const float2*)d_in[1];  // [368,180,513,2]
    const float*  wt   = (const float*)d_in[2];   // [1,1,368,180,513]
    float* out = (float*)d_out;                   // [1,1,368,180]
    (void)in_sizes; (void)n_in; (void)out_size;

    transpose_kernel<<<dim3(IMG_N / 32, IMG_N / 32), dim3(32, 32)>>>(img);
    fp_kernel<<<NRAY / RAYS_PER_BLOCK, 256>>>(img, grid, wt, out);
}

// round 10
// speedup vs baseline: 1.5608x; 1.3610x over previous
#include <cuda_runtime.h>
#include <cstdint>

constexpr int IMG_N  = 256;
constexpr int NDET   = 368;
constexpr int NVIEW  = 180;
constexpr int NSAMP  = 513;
constexpr int NRAY   = NDET * NVIEW;  // 66240
constexpr int RAYS_PER_BLOCK = 8;     // one warp per ray

// Padded image: 2-pixel zero border. Rows=260, row stride=264 (8-float aligned).
constexpr int PB = 2;
constexpr int PW = 264;
constexpr int PH = 260;

__device__ float g_imgP[PH * PW];     // padded normal
__device__ float g_imgTP[PH * PW];    // padded transposed

__global__ void prep_kernel(const float* __restrict__ img)
{
    const int idx = blockIdx.x * 256 + threadIdx.x;
    if (idx >= PH * PW) return;
    const int r = idx / PW, c = idx % PW;
    const int y = r - PB, x = c - PB;
    const bool in = (x >= 0) & (x < IMG_N) & (y >= 0) & (y < IMG_N);
    g_imgP[idx]  = in ? img[y * IMG_N + x] : 0.0f;
    g_imgTP[idx] = in ? img[x * IMG_N + y] : 0.0f;
}

// Bilinear sample on the zero-padded image — no bounds predicates.
// Valid samples have iu,iv in [-1.0, 256.01] (positions are clipped to the
// image box by a_min/a_max), so the clamp is a no-op for them; it only
// tames zero-weight garbage coords. Clamp [-1.5, 256.5] keeps every gather
// strictly inside the padded array: floor range [-2, 256], +PB(+1) <= 259.
__device__ __forceinline__ float bilinP(const float* __restrict__ im,
                                        float u, float v, float wgt)
{
    float iu = fmaf(u, 128.0f, 127.5f);
    float iv = fmaf(v, 128.0f, 127.5f);
    iu = fminf(fmaxf(iu, -1.5f), 256.5f);
    iv = fminf(fmaxf(iv, -1.5f), 256.5f);
    const float fu = floorf(iu);
    const float fv = floorf(iv);
    const int u0 = (int)fu, v0 = (int)fv;
    const float wu1 = iu - fu, wv1 = iv - fv;
    const float wu0 = 1.0f - wu1, wv0 = 1.0f - wv1;

    const float* p = im + (v0 + PB) * PW + (u0 + PB);
    const float a00 = __ldg(p);
    const float a10 = __ldg(p + 1);
    const float a01 = __ldg(p + PW);
    const float a11 = __ldg(p + PW + 1);

    const float top = fmaf(wu1, a10, wu0 * a00);
    const float bot = fmaf(wu1, a11, wu0 * a01);
    return wgt * fmaf(wv1, bot, wv0 * top);
}

template<bool TR>
__device__ __forceinline__ float ray_accum(const float* __restrict__ im,
                                           const float2* __restrict__ g,
                                           const float* __restrict__ w,
                                           int lane)
{
    float acc = 0.0f;
    // 512 samples per warp: 2 chunks of 8 strided batches, s = lane + 32*k.
    #pragma unroll
    for (int c = 0; c < 2; c++) {
        float2 p[8];
        float  pw[8];
        #pragma unroll
        for (int j = 0; j < 8; j++) {
            const int s = lane + 32 * (c * 8 + j);
            p[j]  = __ldcs(&g[s]);
            pw[j] = __ldcs(&w[s]);
        }
        #pragma unroll
        for (int j = 0; j < 8; j++) {
            const float u = TR ? p[j].y : p[j].x;
            const float v = TR ? p[j].x : p[j].y;
            acc += bilinP(im, u, v, pw[j]);
        }
    }
    // Odd tail sample s = 512 (lane 0 only).
    if (lane == 0) {
        const float2 p = __ldg(&g[512]);
        const float  wv = __ldg(&w[512]);
        acc += bilinP(im, TR ? p.y : p.x, TR ? p.x : p.y, wv);
    }
    return acc;
}

__global__ __launch_bounds__(256)
void fp_kernel(const float2* __restrict__ grid,   // [NRAY, NSAMP] (gx, gy)
               const float* __restrict__ wt,      // [NRAY, NSAMP]
               float* __restrict__ out)           // [NRAY]
{
    const int wid  = threadIdx.x >> 5;
    const int lane = threadIdx.x & 31;
    const int ray  = blockIdx.x * RAYS_PER_BLOCK + wid;

    const float2* __restrict__ g = grid + (size_t)ray * NSAMP;
    const float*  __restrict__ w = wt   + (size_t)ray * NSAMP;

    // Per-ray orientation: make the fast-moving coordinate contiguous.
    const float2 ga = __ldg(&g[0]);
    const float2 gb = __ldg(&g[NSAMP - 1]);
    const bool   tr = fabsf(gb.x - ga.x) < fabsf(gb.y - ga.y);

    float acc;
    if (tr) acc = ray_accum<true >(g_imgTP, g, w, lane);
    else    acc = ray_accum<false>(g_imgP,  g, w, lane);

    // Warp reduction — no smem, no barriers.
    #pragma unroll
    for (int o = 16; o > 0; o >>= 1)
        acc += __shfl_down_sync(0xFFFFFFFFu, acc, o);

    if (lane == 0) out[ray] = acc;
}

extern "C" void kernel_launch(void* const* d_in, const int* in_sizes, int n_in,
                              void* d_out, int out_size)
{
    const float*  img  = (const float*)d_in[0];   // [1,1,256,256]
    const float2* grid = (const float2*)d_in[1];  // [368,180,513,2]
    const float*  wt   = (const float*)d_in[2];   // [1,1,368,180,513]
    float* out = (float*)d_out;                   // [1,1,368,180]
    (void)in_sizes; (void)n_in; (void)out_size;

    prep_kernel<<<(PH * PW + 255) / 256, 256>>>(img);
    fp_kernel<<<NRAY / RAYS_PER_BLOCK, 256>>>(grid, wt, out);
}

// round 12
// speedup vs baseline: 1.7691x; 1.1334x over previous
#include <cuda_runtime.h>
#include <cstdint>

constexpr int IMG_N  = 256;
constexpr int NDET   = 368;
constexpr int NVIEW  = 180;
constexpr int NSAMP  = 513;
constexpr int NRAY   = NDET * NVIEW;  // 66240
constexpr int RAYS_PER_BLOCK = 8;     // one warp per ray

// Padded quad images: quad[v][u] = (P(v,u), P(v,u+1), P(v+1,u), P(v+1,u+1))
// where P is the zero-padded image (2-pixel border).
constexpr int PB = 2;
constexpr int PW = 264;
constexpr int PH = 260;

__device__ float4 g_quadP [PH * PW];   // normal orientation
__device__ float4 g_quadTP[PH * PW];   // transposed orientation

__global__ void prep_kernel(const float* __restrict__ img)
{
    const int idx = blockIdx.x * 256 + threadIdx.x;
    if (idx >= PH * PW) return;
    const int r = idx / PW, c = idx % PW;

    // P(r,c) = img[r-PB][c-PB] if in-bounds else 0 ; PT swaps indices.
    auto P = [&](int rr, int cc) -> float {
        const int y = rr - PB, x = cc - PB;
        return ((x >= 0) & (x < IMG_N) & (y >= 0) & (y < IMG_N))
               ? img[y * IMG_N + x] : 0.0f;
    };
    auto PT = [&](int rr, int cc) -> float {
        const int y = rr - PB, x = cc - PB;
        return ((x >= 0) & (x < IMG_N) & (y >= 0) & (y < IMG_N))
               ? img[x * IMG_N + y] : 0.0f;
    };

    g_quadP [idx] = make_float4(P (r, c), P (r, c + 1), P (r + 1, c), P (r + 1, c + 1));
    g_quadTP[idx] = make_float4(PT(r, c), PT(r, c + 1), PT(r + 1, c), PT(r + 1, c + 1));
}

// Bilinear sample: ONE float4 gather fetches all four corners.
// Valid samples have iu,iv in [-1.0, 256.01]; clamp [-1.5, 256.5] is a no-op
// for them and keeps zero-weight garbage coords in-bounds:
// floor in [-2, 256], +PB <= 258 < PH-1, PW-1.
__device__ __forceinline__ float bilinQ(const float4* __restrict__ qim,
                                        float u, float v, float wgt)
{
    float iu = fmaf(u, 128.0f, 127.5f);
    float iv = fmaf(v, 128.0f, 127.5f);
    iu = fminf(fmaxf(iu, -1.5f), 256.5f);
    iv = fminf(fmaxf(iv, -1.5f), 256.5f);
    const float fu = floorf(iu);
    const float fv = floorf(iv);
    const int u0 = (int)fu, v0 = (int)fv;
    const float wu1 = iu - fu, wv1 = iv - fv;
    const float wu0 = 1.0f - wu1, wv0 = 1.0f - wv1;

    const float4 q = __ldg(&qim[(v0 + PB) * PW + (u0 + PB)]);

    const float top = fmaf(wu1, q.y, wu0 * q.x);
    const float bot = fmaf(wu1, q.w, wu0 * q.z);
    return wgt * fmaf(wv1, bot, wv0 * top);
}

template<bool TR>
__device__ __forceinline__ float ray_accum(const float4* __restrict__ qim,
                                           const float2* __restrict__ g,
                                           const float* __restrict__ w,
                                           int lane)
{
    float acc = 0.0f;
    // 512 samples per warp: 2 chunks of 8 strided batches, s = lane + 32*k.
    // Adjacent lanes take adjacent samples -> gather locality.
    #pragma unroll
    for (int c = 0; c < 2; c++) {
        float2 p[8];
        float  pw[8];
        #pragma unroll
        for (int j = 0; j < 8; j++) {
            const int s = lane + 32 * (c * 8 + j);
            p[j]  = __ldcs(&g[s]);
            pw[j] = __ldcs(&w[s]);
        }
        #pragma unroll
        for (int j = 0; j < 8; j++) {
            const float u = TR ? p[j].y : p[j].x;
            const float v = TR ? p[j].x : p[j].y;
            acc += bilinQ(qim, u, v, pw[j]);
        }
    }
    // Odd tail sample s = 512 (lane 0 only).
    if (lane == 0) {
        const float2 p = __ldg(&g[512]);
        const float  wv = __ldg(&w[512]);
        acc += bilinQ(qim, TR ? p.y : p.x, TR ? p.x : p.y, wv);
    }
    return acc;
}

__global__ __launch_bounds__(256, 5)
void fp_kernel(const float2* __restrict__ grid,   // [NRAY, NSAMP] (gx, gy)
               const float* __restrict__ wt,      // [NRAY, NSAMP]
               float* __restrict__ out)           // [NRAY]
{
    const int wid  = threadIdx.x >> 5;
    const int lane = threadIdx.x & 31;
    const int ray  = blockIdx.x * RAYS_PER_BLOCK + wid;

    const float2* __restrict__ g = grid + (size_t)ray * NSAMP;
    const float*  __restrict__ w = wt   + (size_t)ray * NSAMP;

    // Per-ray orientation: make the fast-moving coordinate contiguous.
    const float2 ga = __ldg(&g[0]);
    const float2 gb = __ldg(&g[NSAMP - 1]);
    const bool   tr = fabsf(gb.x - ga.x) < fabsf(gb.y - ga.y);

    float acc;
    if (tr) acc = ray_accum<true >(g_quadTP, g, w, lane);
    else    acc = ray_accum<false>(g_quadP,  g, w, lane);

    // Warp reduction — no smem, no barriers.
    #pragma unroll
    for (int o = 16; o > 0; o >>= 1)
        acc += __shfl_down_sync(0xFFFFFFFFu, acc, o);

    if (lane == 0) out[ray] = acc;
}

extern "C" void kernel_launch(void* const* d_in, const int* in_sizes, int n_in,
                              void* d_out, int out_size)
{
    const float*  img  = (const float*)d_in[0];   // [1,1,256,256]
    const float2* grid = (const float2*)d_in[1];  // [368,180,513,2]
    const float*  wt   = (const float*)d_in[2];   // [1,1,368,180,513]
    float* out = (float*)d_out;                   // [1,1,368,180]
    (void)in_sizes; (void)n_in; (void)out_size;

    prep_kernel<<<(PH * PW + 255) / 256, 256>>>(img);
    fp_kernel<<<NRAY / RAYS_PER_BLOCK, 256>>>(grid, wt, out);
}